// round 13
// baseline (speedup 1.0000x reference)
#include <cuda_runtime.h>
#include <cuda_fp16.h>
#include <cstdint>

#define BATCH 8
#define HH    128
#define WW    128
#define CIN   256
#define COUT  256
#define KTOT  2304           // 9 * CIN
#define NKC   72             // 2304 / 32
#define STAGES 4
#define STAGE_BYTES 24576    // A 16K (256 rows x 64B) + B 8K (32 rows x 256B)
#define SMEM_BYTES (STAGES * STAGE_BYTES)   // 96 KB

// ---------------- static device scratch ----------------
__device__ float g_demod[BATCH * COUT];
__device__ float g_k2t[COUT * CIN];                          // sum_tap w^2, [co][ci]
__device__ __align__(16) __half g_xh[BATCH * HH * WW * CIN]; // x*style (fp16)
__device__ __align__(16) __half g_wh[KTOT * COUT];           // weights fp16 [k][n]

// ---------------- PTX helpers (all plain sm_80-class) ----------------
static __device__ __forceinline__ uint32_t s2u(const void* p) {
    uint32_t a;
    asm("{ .reg .u64 t; cvta.to.shared.u64 t, %1; cvt.u32.u64 %0, t; }"
        : "=r"(a) : "l"(p));
    return a;
}
static __device__ __forceinline__ void cpasync(uint32_t dst, const void* src,
                                               uint32_t srcsz) {
    asm volatile("cp.async.cg.shared.global [%0], [%1], 16, %2;"
                 :: "r"(dst), "l"(src), "r"(srcsz) : "memory");
}
#define CP_COMMIT() asm volatile("cp.async.commit_group;" ::: "memory")
#define CP_WAIT2()  asm volatile("cp.async.wait_group 2;" ::: "memory")

static __device__ __forceinline__ void ldsm4(uint32_t* r, uint32_t a) {
    asm volatile("ldmatrix.sync.aligned.m8n8.x4.shared.b16 {%0,%1,%2,%3}, [%4];"
                 : "=r"(r[0]), "=r"(r[1]), "=r"(r[2]), "=r"(r[3]) : "r"(a));
}
static __device__ __forceinline__ void ldsm4t(uint32_t* r, uint32_t a) {
    asm volatile("ldmatrix.sync.aligned.m8n8.x4.trans.shared.b16 {%0,%1,%2,%3}, [%4];"
                 : "=r"(r[0]), "=r"(r[1]), "=r"(r[2]), "=r"(r[3]) : "r"(a));
}
static __device__ __forceinline__ void mma16816(float* c, const uint32_t* a,
                                                uint32_t b0, uint32_t b1) {
    asm volatile(
        "mma.sync.aligned.m16n8k16.row.col.f32.f16.f16.f32 "
        "{%0,%1,%2,%3}, {%4,%5,%6,%7}, {%8,%9}, {%0,%1,%2,%3};"
        : "+f"(c[0]), "+f"(c[1]), "+f"(c[2]), "+f"(c[3])
        : "r"(a[0]), "r"(a[1]), "r"(a[2]), "r"(a[3]), "r"(b0), "r"(b1));
}

// ---------------- pre-pass kernels ----------------
// Fused weight pass: fp16 convert + tap-reduction of squares (one read of kern)
__global__ void w_pre_kernel(const float* __restrict__ kern) {
    int ci = blockIdx.x;
    int co = threadIdx.x;
    float s = 0.0f;
    #pragma unroll
    for (int tap = 0; tap < 9; ++tap) {
        size_t idx = (size_t)(tap * CIN + ci) * COUT + co;
        float w = kern[idx];
        g_wh[idx] = __float2half_rn(w);
        s = fmaf(w, w, s);
    }
    g_k2t[co * CIN + ci] = s;
}

__global__ __launch_bounds__(256) void demod_kernel(const float* __restrict__ style) {
    int gw   = blockIdx.x * 8 + (threadIdx.x >> 5);   // 0..2047
    int lane = threadIdx.x & 31;
    int b  = gw >> 8;
    int co = gw & 255;
    float acc = 0.0f;
    #pragma unroll
    for (int t = 0; t < 8; ++t) {
        int ci = t * 32 + lane;
        float s = style[b * CIN + ci];
        acc = fmaf(s * s, g_k2t[co * CIN + ci], acc);
    }
    #pragma unroll
    for (int o = 16; o > 0; o >>= 1)
        acc += __shfl_xor_sync(0xFFFFFFFF, acc, o);
    if (lane == 0) g_demod[b * COUT + co] = rsqrtf(acc + 1e-7f);
}

__global__ __launch_bounds__(256) void mod_x_kernel(
    const float* __restrict__ x, const float* __restrict__ style) {
    size_t e = ((size_t)blockIdx.x * 256 + threadIdx.x) * 4;
    int ci = (int)(e & 255);
    int b  = (int)(e >> 22);
    float4 xv = *(const float4*)(x + e);
    float4 sv = *(const float4*)(style + b * CIN + ci);
    __half2 p01 = __floats2half2_rn(xv.x * sv.x, xv.y * sv.y);
    __half2 p23 = __floats2half2_rn(xv.z * sv.z, xv.w * sv.w);
    *(uint2*)(g_xh + e) = make_uint2(*(uint32_t*)&p01, *(uint32_t*)&p23);
}

// ---------------- main mma.sync kernel ----------------
// CTA tile 256(M) x 128(N) x 32(K). 512 threads = 16 warps:
//   wm = wid & 3 (64 M-rows each), wn = wid >> 2 (32 N-cols each).
// Warp tile 64x32, inner loop IDENTICAL to the proven R10 kernel.
// Stage: A @0 (16K: 256 rows x 64B), B @16K (8K: 32 rows x 256B). 4 stages.
// A swizzle: 4 chunks/row: chunk' = c ^ ((row>>1)&3)
// B swizzle: 16 chunks/row: chunk' = c ^ (krow&7)
// 1 CTA/SM (regs 128/thread), smem traffic per MAC 25% lower than 128x128.
__global__ __launch_bounds__(512, 1) void conv_mma_kernel(float* __restrict__ out) {
    extern __shared__ char dsm[];
    const uint32_t smem = s2u(dsm);
    const int tid  = threadIdx.x;
    const int wid  = tid >> 5;
    const int lane = tid & 31;
    const int wm = wid & 3;          // 0..3
    const int wn = wid >> 2;         // 0..3
    const int mt = blockIdx.x;       // 0..511: 256 consecutive m = 2 image rows
    const int n0 = blockIdx.y * 128;
    const int m0 = mt * 256;
    const int b  = m0 >> 14;         // 64 tiles per image: never straddles batch

    // A loader: 256 rows x 4 chunks(16B); 512 threads -> 2 chunks each
    const int arow = tid >> 1;          // 0..255
    const int ac0  = (tid & 1) * 2;     // chunk base {0, 2}
    const int am   = m0 + arow;
    const int ahy  = (am >> 7) & 127;   // per-row image y
    const int awx  = am & 127;          // image x
    // B loader: 32 rows x 16 chunks; 512 threads -> 1 chunk each
    const int brow = tid >> 4;          // 0..31
    const int bc   = tid & 15;

    auto load_stage = [&](int kc, int stage) {
        const uint32_t sb = smem + (uint32_t)stage * STAGE_BYTES;
        const int tap = kc >> 3;
        const int ci0 = (kc & 7) << 5;
        const int dh  = tap / 3;
        const int dw  = tap - dh * 3;
        const int ih  = ahy + dh - 1;
        const int iw  = awx + dw - 1;
        const bool v  = ((unsigned)ih < HH) && ((unsigned)iw < WW);
        const uint32_t sz = v ? 16u : 0u;
        const size_t gA = (((size_t)b * HH + (v ? ih : 0)) * WW + (v ? iw : 0)) * CIN + ci0;
        const uint32_t da = sb + (uint32_t)arow * 64u;
        #pragma unroll
        for (int j = 0; j < 2; ++j) {
            int c = ac0 + j;
            uint32_t off = (uint32_t)((c ^ ((arow >> 1) & 3)) * 16);
            cpasync(da + off, g_xh + gA + c * 8, sz);
        }
        const size_t gB = (size_t)(kc * 32 + brow) * COUT + n0;
        const uint32_t db = sb + 16384u + (uint32_t)brow * 256u;
        uint32_t off = (uint32_t)((bc ^ (brow & 7)) * 16);
        cpasync(db + off, g_wh + gB + bc * 8, 16u);
    };

    // ldmatrix lane constants (identical to R10)
    const int lr = lane & 7;
    const int lg = lane >> 3;
    const int cg = lg >> 1;
    int rowA[4];
    #pragma unroll
    for (int mb = 0; mb < 4; ++mb)
        rowA[mb] = wm * 64 + mb * 16 + lr + (lg & 1) * 8;
    const int rkb = (lg & 1) * 8 + lr;

    float acc[4][4][4];
    #pragma unroll
    for (int mb = 0; mb < 4; ++mb)
        #pragma unroll
        for (int nb = 0; nb < 4; ++nb)
            #pragma unroll
            for (int q = 0; q < 4; ++q) acc[mb][nb][q] = 0.0f;

    load_stage(0, 0); CP_COMMIT();
    load_stage(1, 1); CP_COMMIT();
    load_stage(2, 2); CP_COMMIT();

    for (int kc = 0; kc < NKC; ++kc) {
        CP_WAIT2();
        __syncthreads();
        const int nk = kc + STAGES - 1;
        if (nk < NKC) load_stage(nk, nk & (STAGES - 1));
        CP_COMMIT();

        const uint32_t sb = smem + (uint32_t)(kc & (STAGES - 1)) * STAGE_BYTES;
        #pragma unroll
        for (int ks = 0; ks < 2; ++ks) {
            uint32_t a[4][4], bh[2][4];
            #pragma unroll
            for (int mb = 0; mb < 4; ++mb) {
                int ch = 2 * ks + cg;
                ldsm4(a[mb], sb + (uint32_t)(rowA[mb] * 64 +
                             ((ch ^ ((rowA[mb] >> 1) & 3)) * 16)));
            }
            #pragma unroll
            for (int h2 = 0; h2 < 2; ++h2) {
                int rk = ks * 16 + rkb;
                int ch = wn * 4 + h2 * 2 + cg;
                ldsm4t(bh[h2], sb + 16384u + (uint32_t)(rk * 256 +
                               ((ch ^ (rk & 7)) * 16)));
            }
            #pragma unroll
            for (int mb = 0; mb < 4; ++mb)
                #pragma unroll
                for (int nb = 0; nb < 4; ++nb)
                    mma16816(acc[mb][nb], a[mb],
                             bh[nb >> 1][2 * (nb & 1)], bh[nb >> 1][2 * (nb & 1) + 1]);
        }
        __syncthreads();
    }

    // ---- epilogue: demod + store ----
    const int mbase = m0 + wm * 64;
    const int nbase = n0 + wn * 32;
    const float* dmp = g_demod + b * COUT;
    float dm[4][2];
    #pragma unroll
    for (int nb = 0; nb < 4; ++nb) {
        int n = nbase + nb * 8 + (lane & 3) * 2;
        dm[nb][0] = __ldg(dmp + n);
        dm[nb][1] = __ldg(dmp + n + 1);
    }
    #pragma unroll
    for (int mb = 0; mb < 4; ++mb) {
        #pragma unroll
        for (int r2 = 0; r2 < 2; ++r2) {
            int m = mbase + mb * 16 + (lane >> 2) + r2 * 8;
            float* op = out + (size_t)m * COUT;
            #pragma unroll
            for (int nb = 0; nb < 4; ++nb) {
                int n = nbase + nb * 8 + (lane & 3) * 2;
                float2 v;
                v.x = acc[mb][nb][2 * r2]     * dm[nb][0];
                v.y = acc[mb][nb][2 * r2 + 1] * dm[nb][1];
                *(float2*)(op + n) = v;
            }
        }
    }
}

// ---------------- host launch ----------------
extern "C" void kernel_launch(void* const* d_in, const int* in_sizes, int n_in,
                              void* d_out, int out_size) {
    const float* x     = (const float*)d_in[0];   // (8,128,128,256)
    const float* style = (const float*)d_in[1];   // (8,256)
    const float* kern  = (const float*)d_in[2];   // (3,3,256,256)
    float* out = (float*)d_out;

    w_pre_kernel<<<CIN, COUT>>>(kern);
    mod_x_kernel<<<(BATCH * HH * WW * CIN) / 4 / 256, 256>>>(x, style);
    demod_kernel<<<256, 256>>>(style);

    cudaFuncSetAttribute(conv_mma_kernel,
                         cudaFuncAttributeMaxDynamicSharedMemorySize, SMEM_BYTES);
    dim3 grid(512, 2);
    conv_mma_kernel<<<grid, 512, SMEM_BYTES>>>(out);
}

// round 14
// speedup vs baseline: 1.2393x; 1.2393x over previous
#include <cuda_runtime.h>
#include <cuda_fp16.h>
#include <cstdint>

#define BATCH 8
#define HH    128
#define WW    128
#define CIN   256
#define COUT  256
#define KTOT  2304           // 9 * CIN
#define NKC   72             // 2304 / 32
#define STAGES 4
#define STAGE_BYTES 16384    // A 8K + B 8K
#define SMEM_BYTES (STAGES * STAGE_BYTES)

// ---------------- static device scratch ----------------
__device__ float g_demod[BATCH * COUT];
__device__ float g_k2t[COUT * CIN];                          // sum_tap w^2, [co][ci]
__device__ __align__(16) __half g_xh[BATCH * HH * WW * CIN]; // x*style (fp16)
__device__ __align__(16) __half g_wh[KTOT * COUT];           // weights fp16 [k][n]

// ---------------- PTX helpers (all plain sm_80-class) ----------------
static __device__ __forceinline__ uint32_t s2u(const void* p) {
    uint32_t a;
    asm("{ .reg .u64 t; cvta.to.shared.u64 t, %1; cvt.u32.u64 %0, t; }"
        : "=r"(a) : "l"(p));
    return a;
}
static __device__ __forceinline__ void cpasync(uint32_t dst, const void* src,
                                               uint32_t srcsz) {
    asm volatile("cp.async.cg.shared.global [%0], [%1], 16, %2;"
                 :: "r"(dst), "l"(src), "r"(srcsz) : "memory");
}
#define CP_COMMIT() asm volatile("cp.async.commit_group;" ::: "memory")
#define CP_WAIT2()  asm volatile("cp.async.wait_group 2;" ::: "memory")

static __device__ __forceinline__ void ldsm4(uint32_t* r, uint32_t a) {
    asm volatile("ldmatrix.sync.aligned.m8n8.x4.shared.b16 {%0,%1,%2,%3}, [%4];"
                 : "=r"(r[0]), "=r"(r[1]), "=r"(r[2]), "=r"(r[3]) : "r"(a));
}
static __device__ __forceinline__ void ldsm4t(uint32_t* r, uint32_t a) {
    asm volatile("ldmatrix.sync.aligned.m8n8.x4.trans.shared.b16 {%0,%1,%2,%3}, [%4];"
                 : "=r"(r[0]), "=r"(r[1]), "=r"(r[2]), "=r"(r[3]) : "r"(a));
}
static __device__ __forceinline__ void mma16816(float* c, const uint32_t* a,
                                                uint32_t b0, uint32_t b1) {
    asm volatile(
        "mma.sync.aligned.m16n8k16.row.col.f32.f16.f16.f32 "
        "{%0,%1,%2,%3}, {%4,%5,%6,%7}, {%8,%9}, {%0,%1,%2,%3};"
        : "+f"(c[0]), "+f"(c[1]), "+f"(c[2]), "+f"(c[3])
        : "r"(a[0]), "r"(a[1]), "r"(a[2]), "r"(a[3]), "r"(b0), "r"(b1));
}

// ---------------- pre-pass kernels ----------------
// Fused weight pass: fp16 convert + tap-reduction of squares (one read of kern)
__global__ void w_pre_kernel(const float* __restrict__ kern) {
    int ci = blockIdx.x;
    int co = threadIdx.x;
    float s = 0.0f;
    #pragma unroll
    for (int tap = 0; tap < 9; ++tap) {
        size_t idx = (size_t)(tap * CIN + ci) * COUT + co;
        float w = kern[idx];
        g_wh[idx] = __float2half_rn(w);
        s = fmaf(w, w, s);
    }
    g_k2t[co * CIN + ci] = s;
}

__global__ __launch_bounds__(256) void demod_kernel(const float* __restrict__ style) {
    int gw   = blockIdx.x * 8 + (threadIdx.x >> 5);   // 0..2047
    int lane = threadIdx.x & 31;
    int b  = gw >> 8;
    int co = gw & 255;
    float acc = 0.0f;
    #pragma unroll
    for (int t = 0; t < 8; ++t) {
        int ci = t * 32 + lane;
        float s = style[b * CIN + ci];
        acc = fmaf(s * s, g_k2t[co * CIN + ci], acc);
    }
    #pragma unroll
    for (int o = 16; o > 0; o >>= 1)
        acc += __shfl_xor_sync(0xFFFFFFFF, acc, o);
    if (lane == 0) g_demod[b * COUT + co] = rsqrtf(acc + 1e-7f);
}

__global__ __launch_bounds__(256) void mod_x_kernel(
    const float* __restrict__ x, const float* __restrict__ style) {
    size_t e = ((size_t)blockIdx.x * 256 + threadIdx.x) * 4;
    int ci = (int)(e & 255);
    int b  = (int)(e >> 22);
    float4 xv = *(const float4*)(x + e);
    float4 sv = *(const float4*)(style + b * CIN + ci);
    __half2 p01 = __floats2half2_rn(xv.x * sv.x, xv.y * sv.y);
    __half2 p23 = __floats2half2_rn(xv.z * sv.z, xv.w * sv.w);
    *(uint2*)(g_xh + e) = make_uint2(*(uint32_t*)&p01, *(uint32_t*)&p23);
}

// ---------------- main mma.sync kernel (R10 structure, verbatim) ----------------
// CTA tile 128(M) x 128(N) x 32(K). 8 warps: wm in {0,1}, wn in {0..3}.
// Single-product fp16: acc += A*B.
// smem stage: A @0 (8K), B @8K (8K). 4 stages. 2 CTAs/SM.
// A swizzle: 128 rows x 4 chunks(16B): chunk' = c ^ ((row>>1)&3)
// B swizzle: 32 rows x 16 chunks:      chunk' = c ^ (krow&7)
// Grid is (2, 1024): consecutive block IDs share the same A tile (L2 reuse).
__global__ __launch_bounds__(256, 2) void conv_mma_kernel(float* __restrict__ out) {
    extern __shared__ char dsm[];
    const uint32_t smem = s2u(dsm);
    const int tid  = threadIdx.x;
    const int wid  = tid >> 5;
    const int lane = tid & 31;
    const int wm = wid & 1;
    const int wn = wid >> 1;
    const int mt = blockIdx.y;       // 128 consecutive m = one image row
    const int n0 = blockIdx.x * 128;
    const int b  = mt >> 7;
    const int h  = mt & 127;
    const int m0 = mt * 128;

    const int arow = tid >> 1;          // 0..127 = w pixel
    const int ac0  = (tid & 1) * 2;     // A chunk base (2 chunks of 16B)
    const int brow = tid >> 3;          // 0..31 = k row
    const int bc0  = (tid & 7) * 2;     // B chunk base

    auto load_stage = [&](int kc, int stage) {
        const uint32_t sb = smem + (uint32_t)stage * STAGE_BYTES;
        const int tap = kc >> 3;
        const int ci0 = (kc & 7) << 5;
        const int dh  = tap / 3;
        const int dw  = tap - dh * 3;
        const int ih  = h + dh - 1;
        const int iw  = arow + dw - 1;
        const bool v  = ((unsigned)ih < HH) && ((unsigned)iw < WW);
        const uint32_t sz = v ? 16u : 0u;
        const size_t gA = (((size_t)b * HH + (v ? ih : 0)) * WW + (v ? iw : 0)) * CIN + ci0;
        const uint32_t da = sb + (uint32_t)arow * 64u;
        #pragma unroll
        for (int j = 0; j < 2; ++j) {
            int c = ac0 + j;
            uint32_t off = (uint32_t)((c ^ ((arow >> 1) & 3)) * 16);
            cpasync(da + off, g_xh + gA + c * 8, sz);
        }
        const size_t gB = (size_t)(kc * 32 + brow) * COUT + n0;
        const uint32_t db = sb + 8192u + (uint32_t)brow * 256u;
        #pragma unroll
        for (int j = 0; j < 2; ++j) {
            int c = bc0 + j;
            uint32_t off = (uint32_t)((c ^ (brow & 7)) * 16);
            cpasync(db + off, g_wh + gB + c * 8, 16u);
        }
    };

    const int lr = lane & 7;
    const int lg = lane >> 3;
    const int cg = lg >> 1;
    int rowA[4];
    #pragma unroll
    for (int mb = 0; mb < 4; ++mb)
        rowA[mb] = wm * 64 + mb * 16 + lr + (lg & 1) * 8;
    const int rkb = (lg & 1) * 8 + lr;

    float acc[4][4][4];
    #pragma unroll
    for (int mb = 0; mb < 4; ++mb)
        #pragma unroll
        for (int nb = 0; nb < 4; ++nb)
            #pragma unroll
            for (int q = 0; q < 4; ++q) acc[mb][nb][q] = 0.0f;

    load_stage(0, 0); CP_COMMIT();
    load_stage(1, 1); CP_COMMIT();
    load_stage(2, 2); CP_COMMIT();

    for (int kc = 0; kc < NKC; ++kc) {
        CP_WAIT2();
        __syncthreads();
        const int nk = kc + STAGES - 1;
        if (nk < NKC) load_stage(nk, nk & (STAGES - 1));
        CP_COMMIT();

        const uint32_t sb = smem + (uint32_t)(kc & (STAGES - 1)) * STAGE_BYTES;
        #pragma unroll
        for (int ks = 0; ks < 2; ++ks) {
            uint32_t a[4][4], bh[2][4];
            #pragma unroll
            for (int mb = 0; mb < 4; ++mb) {
                int ch = 2 * ks + cg;
                ldsm4(a[mb], sb + (uint32_t)(rowA[mb] * 64 +
                             ((ch ^ ((rowA[mb] >> 1) & 3)) * 16)));
            }
            #pragma unroll
            for (int h2 = 0; h2 < 2; ++h2) {
                int rk = ks * 16 + rkb;
                int ch = wn * 4 + h2 * 2 + cg;
                ldsm4t(bh[h2], sb + 8192u + (uint32_t)(rk * 256 +
                               ((ch ^ (rk & 7)) * 16)));
            }
            #pragma unroll
            for (int mb = 0; mb < 4; ++mb)
                #pragma unroll
                for (int nb = 0; nb < 4; ++nb)
                    mma16816(acc[mb][nb], a[mb],
                             bh[nb >> 1][2 * (nb & 1)], bh[nb >> 1][2 * (nb & 1) + 1]);
        }
        __syncthreads();
    }

    // ---- epilogue: demod + store ----
    const int mbase = m0 + wm * 64;
    const int nbase = n0 + wn * 32;
    const float* dmp = g_demod + b * COUT;
    float dm[4][2];
    #pragma unroll
    for (int nb = 0; nb < 4; ++nb) {
        int n = nbase + nb * 8 + (lane & 3) * 2;
        dm[nb][0] = __ldg(dmp + n);
        dm[nb][1] = __ldg(dmp + n + 1);
    }
    #pragma unroll
    for (int mb = 0; mb < 4; ++mb) {
        #pragma unroll
        for (int r2 = 0; r2 < 2; ++r2) {
            int m = mbase + mb * 16 + (lane >> 2) + r2 * 8;
            float* op = out + (size_t)m * COUT;
            #pragma unroll
            for (int nb = 0; nb < 4; ++nb) {
                int n = nbase + nb * 8 + (lane & 3) * 2;
                float2 v;
                v.x = acc[mb][nb][2 * r2]     * dm[nb][0];
                v.y = acc[mb][nb][2 * r2 + 1] * dm[nb][1];
                *(float2*)(op + n) = v;
            }
        }
    }
}

// ---------------- host launch ----------------
extern "C" void kernel_launch(void* const* d_in, const int* in_sizes, int n_in,
                              void* d_out, int out_size) {
    const float* x     = (const float*)d_in[0];   // (8,128,128,256)
    const float* style = (const float*)d_in[1];   // (8,256)
    const float* kern  = (const float*)d_in[2];   // (3,3,256,256)
    float* out = (float*)d_out;

    w_pre_kernel<<<CIN, COUT>>>(kern);
    mod_x_kernel<<<(BATCH * HH * WW * CIN) / 4 / 256, 256>>>(x, style);
    demod_kernel<<<256, 256>>>(style);

    cudaFuncSetAttribute(conv_mma_kernel,
                         cudaFuncAttributeMaxDynamicSharedMemorySize, SMEM_BYTES);
    dim3 grid(2, 1024);
    conv_mma_kernel<<<grid, 256, SMEM_BYTES>>>(out);
}

// round 16
// speedup vs baseline: 1.2557x; 1.0132x over previous
#include <cuda_runtime.h>
#include <cuda_fp16.h>
#include <cstdint>

#define BATCH 8
#define HH    128
#define WW    128
#define CIN   256
#define COUT  256
#define KTOT  2304           // 9 * CIN
#define NKC   72             // 2304 / 32
#define STAGES 4
#define STAGE_BYTES 16384    // A 8K + B 8K
#define SMEM_BYTES (STAGES * STAGE_BYTES)

// ---------------- static device scratch ----------------
__device__ float g_demod[BATCH * COUT];
__device__ float g_k2t[COUT * CIN];                          // sum_tap w^2, [co][ci]
__device__ __align__(16) __half g_xh[BATCH * HH * WW * CIN]; // x*style (fp16)
__device__ __align__(16) __half g_wh[KTOT * COUT];           // weights fp16 [k][n]

// ---------------- PTX helpers (all plain sm_80-class) ----------------
static __device__ __forceinline__ uint32_t s2u(const void* p) {
    uint32_t a;
    asm("{ .reg .u64 t; cvta.to.shared.u64 t, %1; cvt.u32.u64 %0, t; }"
        : "=r"(a) : "l"(p));
    return a;
}
static __device__ __forceinline__ void cpasync(uint32_t dst, const void* src,
                                               uint32_t srcsz) {
    asm volatile("cp.async.cg.shared.global [%0], [%1], 16, %2;"
                 :: "r"(dst), "l"(src), "r"(srcsz) : "memory");
}
#define CP_COMMIT() asm volatile("cp.async.commit_group;" ::: "memory")
#define CP_WAIT2()  asm volatile("cp.async.wait_group 2;" ::: "memory")

static __device__ __forceinline__ void ldsm4(uint32_t* r, uint32_t a) {
    asm volatile("ldmatrix.sync.aligned.m8n8.x4.shared.b16 {%0,%1,%2,%3}, [%4];"
                 : "=r"(r[0]), "=r"(r[1]), "=r"(r[2]), "=r"(r[3]) : "r"(a));
}
static __device__ __forceinline__ void ldsm4t(uint32_t* r, uint32_t a) {
    asm volatile("ldmatrix.sync.aligned.m8n8.x4.trans.shared.b16 {%0,%1,%2,%3}, [%4];"
                 : "=r"(r[0]), "=r"(r[1]), "=r"(r[2]), "=r"(r[3]) : "r"(a));
}
static __device__ __forceinline__ void mma16816(float* c, const uint32_t* a,
                                                uint32_t b0, uint32_t b1) {
    asm volatile(
        "mma.sync.aligned.m16n8k16.row.col.f32.f16.f16.f32 "
        "{%0,%1,%2,%3}, {%4,%5,%6,%7}, {%8,%9}, {%0,%1,%2,%3};"
        : "+f"(c[0]), "+f"(c[1]), "+f"(c[2]), "+f"(c[3])
        : "r"(a[0]), "r"(a[1]), "r"(a[2]), "r"(a[3]), "r"(b0), "r"(b1));
}

// ---------------- pre-pass kernels ----------------
// Fused pre-pass: blocks [0, 32768) modulate+convert x; blocks [32768, 33024)
// convert weights + tap-reduce squares. One launch, overlapping streams.
// XBLOCKS = BATCH*HH*WW*CIN / 4 / 256 = 32768  (R15 had 16384: half of x stale)
#define XBLOCKS 32768
__global__ __launch_bounds__(256) void pre_kernel(
    const float* __restrict__ x, const float* __restrict__ style,
    const float* __restrict__ kern) {
    if (blockIdx.x < XBLOCKS) {
        size_t e = ((size_t)blockIdx.x * 256 + threadIdx.x) * 4;
        int ci = (int)(e & 255);
        int b  = (int)(e >> 22);
        float4 xv = *(const float4*)(x + e);
        float4 sv = *(const float4*)(style + b * CIN + ci);
        __half2 p01 = __floats2half2_rn(xv.x * sv.x, xv.y * sv.y);
        __half2 p23 = __floats2half2_rn(xv.z * sv.z, xv.w * sv.w);
        *(uint2*)(g_xh + e) = make_uint2(*(uint32_t*)&p01, *(uint32_t*)&p23);
    } else {
        int ci = blockIdx.x - XBLOCKS;
        int co = threadIdx.x;
        float s = 0.0f;
        #pragma unroll
        for (int tap = 0; tap < 9; ++tap) {
            size_t idx = (size_t)(tap * CIN + ci) * COUT + co;
            float w = kern[idx];
            g_wh[idx] = __float2half_rn(w);
            s = fmaf(w, w, s);
        }
        g_k2t[co * CIN + ci] = s;
    }
}

__global__ __launch_bounds__(256) void demod_kernel(const float* __restrict__ style) {
    int gw   = blockIdx.x * 8 + (threadIdx.x >> 5);   // 0..2047
    int lane = threadIdx.x & 31;
    int b  = gw >> 8;
    int co = gw & 255;
    float acc = 0.0f;
    #pragma unroll
    for (int t = 0; t < 8; ++t) {
        int ci = t * 32 + lane;
        float s = style[b * CIN + ci];
        acc = fmaf(s * s, g_k2t[co * CIN + ci], acc);
    }
    #pragma unroll
    for (int o = 16; o > 0; o >>= 1)
        acc += __shfl_xor_sync(0xFFFFFFFF, acc, o);
    if (lane == 0) g_demod[b * COUT + co] = rsqrtf(acc + 1e-7f);
}

// ---------------- main mma.sync kernel (R14 + trailing-barrier removal + unroll) --
// CTA tile 128(M) x 128(N) x 32(K). 8 warps: wm in {0,1}, wn in {0..3}.
// Single-product fp16: acc += A*B.
// smem stage: A @0 (8K), B @8K (8K). 4 stages. 2 CTAs/SM.
// A swizzle: 128 rows x 4 chunks(16B): chunk' = c ^ ((row>>1)&3)
// B swizzle: 32 rows x 16 chunks:      chunk' = c ^ (krow&7)
// One barrier per iter: the top-of-loop __syncthreads at kc orders all reads of
// stage (kc-1)&3 (performed before each warp reached the barrier) against the
// loader's cp.async writes to that stage (issued after the barrier).
// Grid (2, 1024): consecutive blocks share A tiles in L2.
__global__ __launch_bounds__(256, 2) void conv_mma_kernel(float* __restrict__ out) {
    extern __shared__ char dsm[];
    const uint32_t smem = s2u(dsm);
    const int tid  = threadIdx.x;
    const int wid  = tid >> 5;
    const int lane = tid & 31;
    const int wm = wid & 1;
    const int wn = wid >> 1;
    const int mt = blockIdx.y;       // 128 consecutive m = one image row
    const int n0 = blockIdx.x * 128;
    const int b  = mt >> 7;
    const int h  = mt & 127;
    const int m0 = mt * 128;

    const int arow = tid >> 1;          // 0..127 = w pixel
    const int ac0  = (tid & 1) * 2;     // A chunk base (2 chunks of 16B)
    const int brow = tid >> 3;          // 0..31 = k row
    const int bc0  = (tid & 7) * 2;     // B chunk base

    auto load_stage = [&](int kc, int stage) {
        const uint32_t sb = smem + (uint32_t)stage * STAGE_BYTES;
        const int tap = kc >> 3;
        const int ci0 = (kc & 7) << 5;
        const int dh  = tap / 3;
        const int dw  = tap - dh * 3;
        const int ih  = h + dh - 1;
        const int iw  = arow + dw - 1;
        const bool v  = ((unsigned)ih < HH) && ((unsigned)iw < WW);
        const uint32_t sz = v ? 16u : 0u;
        const size_t gA = (((size_t)b * HH + (v ? ih : 0)) * WW + (v ? iw : 0)) * CIN + ci0;
        const uint32_t da = sb + (uint32_t)arow * 64u;
        #pragma unroll
        for (int j = 0; j < 2; ++j) {
            int c = ac0 + j;
            uint32_t off = (uint32_t)((c ^ ((arow >> 1) & 3)) * 16);
            cpasync(da + off, g_xh + gA + c * 8, sz);
        }
        const size_t gB = (size_t)(kc * 32 + brow) * COUT + n0;
        const uint32_t db = sb + 8192u + (uint32_t)brow * 256u;
        #pragma unroll
        for (int j = 0; j < 2; ++j) {
            int c = bc0 + j;
            uint32_t off = (uint32_t)((c ^ (brow & 7)) * 16);
            cpasync(db + off, g_wh + gB + c * 8, 16u);
        }
    };

    const int lr = lane & 7;
    const int lg = lane >> 3;
    const int cg = lg >> 1;
    int rowA[4];
    #pragma unroll
    for (int mb = 0; mb < 4; ++mb)
        rowA[mb] = wm * 64 + mb * 16 + lr + (lg & 1) * 8;
    const int rkb = (lg & 1) * 8 + lr;

    float acc[4][4][4];
    #pragma unroll
    for (int mb = 0; mb < 4; ++mb)
        #pragma unroll
        for (int nb = 0; nb < 4; ++nb)
            #pragma unroll
            for (int q = 0; q < 4; ++q) acc[mb][nb][q] = 0.0f;

    load_stage(0, 0); CP_COMMIT();
    load_stage(1, 1); CP_COMMIT();
    load_stage(2, 2); CP_COMMIT();

    #pragma unroll 4
    for (int kc = 0; kc < NKC; ++kc) {
        CP_WAIT2();
        __syncthreads();
        const int nk = kc + STAGES - 1;
        if (nk < NKC) load_stage(nk, nk & (STAGES - 1));
        CP_COMMIT();

        const uint32_t sb = smem + (uint32_t)(kc & (STAGES - 1)) * STAGE_BYTES;
        #pragma unroll
        for (int ks = 0; ks < 2; ++ks) {
            uint32_t a[4][4], bh[2][4];
            #pragma unroll
            for (int mb = 0; mb < 4; ++mb) {
                int ch = 2 * ks + cg;
                ldsm4(a[mb], sb + (uint32_t)(rowA[mb] * 64 +
                             ((ch ^ ((rowA[mb] >> 1) & 3)) * 16)));
            }
            #pragma unroll
            for (int h2 = 0; h2 < 2; ++h2) {
                int rk = ks * 16 + rkb;
                int ch = wn * 4 + h2 * 2 + cg;
                ldsm4t(bh[h2], sb + 8192u + (uint32_t)(rk * 256 +
                               ((ch ^ (rk & 7)) * 16)));
            }
            #pragma unroll
            for (int mb = 0; mb < 4; ++mb)
                #pragma unroll
                for (int nb = 0; nb < 4; ++nb)
                    mma16816(acc[mb][nb], a[mb],
                             bh[nb >> 1][2 * (nb & 1)], bh[nb >> 1][2 * (nb & 1) + 1]);
        }
        // no trailing __syncthreads: next iteration's top barrier provides the
        // read->overwrite ordering for stage reuse (see header comment)
    }

    // ---- epilogue: demod + store ----
    const int mbase = m0 + wm * 64;
    const int nbase = n0 + wn * 32;
    const float* dmp = g_demod + b * COUT;
    float dm[4][2];
    #pragma unroll
    for (int nb = 0; nb < 4; ++nb) {
        int n = nbase + nb * 8 + (lane & 3) * 2;
        dm[nb][0] = __ldg(dmp + n);
        dm[nb][1] = __ldg(dmp + n + 1);
    }
    #pragma unroll
    for (int mb = 0; mb < 4; ++mb) {
        #pragma unroll
        for (int r2 = 0; r2 < 2; ++r2) {
            int m = mbase + mb * 16 + (lane >> 2) + r2 * 8;
            float* op = out + (size_t)m * COUT;
            #pragma unroll
            for (int nb = 0; nb < 4; ++nb) {
                int n = nbase + nb * 8 + (lane & 3) * 2;
                float2 v;
                v.x = acc[mb][nb][2 * r2]     * dm[nb][0];
                v.y = acc[mb][nb][2 * r2 + 1] * dm[nb][1];
                *(float2*)(op + n) = v;
            }
        }
    }
}

// ---------------- host launch ----------------
extern "C" void kernel_launch(void* const* d_in, const int* in_sizes, int n_in,
                              void* d_out, int out_size) {
    const float* x     = (const float*)d_in[0];   // (8,128,128,256)
    const float* style = (const float*)d_in[1];   // (8,256)
    const float* kern  = (const float*)d_in[2];   // (3,3,256,256)
    float* out = (float*)d_out;

    pre_kernel<<<XBLOCKS + CIN, 256>>>(x, style, kern);
    demod_kernel<<<256, 256>>>(style);

    cudaFuncSetAttribute(conv_mma_kernel,
                         cudaFuncAttributeMaxDynamicSharedMemorySize, SMEM_BYTES);
    dim3 grid(2, 1024);
    conv_mma_kernel<<<grid, 256, SMEM_BYTES>>>(out);
}

// round 17
// speedup vs baseline: 1.4467x; 1.1521x over previous
#include <cuda_runtime.h>
#include <cuda_fp16.h>
#include <cuda.h>
#include <cstdint>

#define BATCH 8
#define HH    128
#define WW    128
#define CIN   256
#define COUT  256
#define KTOT  2304           // 9 * CIN
#define NKC   72             // 2304 / 32
#define STAGES 4
#define STAGE_BYTES 16384    // A 8K (128 rows x 64B, SW64) + B 8K (2 halves x 32 rows x 128B, SW128)
// smem: [0,64) mbarriers, stages at +1024.  +1024 slack for manual alignment.
#define SMEM_REQ (1024 + STAGES * STAGE_BYTES + 1024)

// ---------------- static device scratch ----------------
__device__ float g_demod[BATCH * COUT];
__device__ float g_k2t[COUT * CIN];                                   // sum_tap w^2
__device__ __align__(1024) __half g_xh[BATCH * HH * WW * CIN];        // x*style fp16
__device__ __align__(1024) __half g_wh[KTOT * COUT];                  // weights fp16 [k][n]

// ---------------- PTX helpers ----------------
static __device__ __forceinline__ uint32_t s2u(const void* p) {
    uint32_t a;
    asm("{ .reg .u64 t; cvta.to.shared.u64 t, %1; cvt.u32.u64 %0, t; }"
        : "=r"(a) : "l"(p));
    return a;
}
static __device__ __forceinline__ void mbar_init(uint32_t mb, uint32_t cnt) {
    asm volatile("mbarrier.init.shared.b64 [%0], %1;" :: "r"(mb), "r"(cnt) : "memory");
}
static __device__ __forceinline__ void mbar_expect(uint32_t mb, uint32_t bytes) {
    asm volatile("mbarrier.arrive.expect_tx.shared.b64 _, [%0], %1;"
                 :: "r"(mb), "r"(bytes) : "memory");
}
static __device__ __forceinline__ void mbar_wait(uint32_t mb, uint32_t phase) {
    asm volatile(
        "{\n\t.reg .pred P;\n\t"
        "WL_%=:\n\t"
        "mbarrier.try_wait.parity.acquire.cta.shared::cta.b64 P, [%0], %1, 0x989680;\n\t"
        "@P bra WD_%=;\n\t"
        "bra WL_%=;\n\t"
        "WD_%=:\n\t}"
        :: "r"(mb), "r"(phase) : "memory");
}
static __device__ __forceinline__ void tma4(uint32_t dst, const CUtensorMap* tm,
                                            int c0, int c1, int c2, int c3, uint32_t mb) {
    asm volatile(
        "cp.async.bulk.tensor.4d.shared::cta.global.tile.mbarrier::complete_tx::bytes "
        "[%0], [%1, {%2, %3, %4, %5}], [%6];"
        :: "r"(dst), "l"(tm), "r"(c0), "r"(c1), "r"(c2), "r"(c3), "r"(mb) : "memory");
}
static __device__ __forceinline__ void tma2(uint32_t dst, const CUtensorMap* tm,
                                            int c0, int c1, uint32_t mb) {
    asm volatile(
        "cp.async.bulk.tensor.2d.shared::cta.global.tile.mbarrier::complete_tx::bytes "
        "[%0], [%1, {%2, %3}], [%4];"
        :: "r"(dst), "l"(tm), "r"(c0), "r"(c1), "r"(mb) : "memory");
}
#define FENCE_ASYNC() asm volatile("fence.proxy.async.shared::cta;" ::: "memory")

static __device__ __forceinline__ void ldsm4(uint32_t* r, uint32_t a) {
    asm volatile("ldmatrix.sync.aligned.m8n8.x4.shared.b16 {%0,%1,%2,%3}, [%4];"
                 : "=r"(r[0]), "=r"(r[1]), "=r"(r[2]), "=r"(r[3]) : "r"(a));
}
static __device__ __forceinline__ void ldsm4t(uint32_t* r, uint32_t a) {
    asm volatile("ldmatrix.sync.aligned.m8n8.x4.trans.shared.b16 {%0,%1,%2,%3}, [%4];"
                 : "=r"(r[0]), "=r"(r[1]), "=r"(r[2]), "=r"(r[3]) : "r"(a));
}
static __device__ __forceinline__ void mma16816(float* c, const uint32_t* a,
                                                uint32_t b0, uint32_t b1) {
    asm volatile(
        "mma.sync.aligned.m16n8k16.row.col.f32.f16.f16.f32 "
        "{%0,%1,%2,%3}, {%4,%5,%6,%7}, {%8,%9}, {%0,%1,%2,%3};"
        : "+f"(c[0]), "+f"(c[1]), "+f"(c[2]), "+f"(c[3])
        : "r"(a[0]), "r"(a[1]), "r"(a[2]), "r"(a[3]), "r"(b0), "r"(b1));
}

// ---------------- pre-pass kernels (unchanged from R16 winner) ----------------
#define XBLOCKS 32768
__global__ __launch_bounds__(256) void pre_kernel(
    const float* __restrict__ x, const float* __restrict__ style,
    const float* __restrict__ kern) {
    if (blockIdx.x < XBLOCKS) {
        size_t e = ((size_t)blockIdx.x * 256 + threadIdx.x) * 4;
        int ci = (int)(e & 255);
        int b  = (int)(e >> 22);
        float4 xv = *(const float4*)(x + e);
        float4 sv = *(const float4*)(style + b * CIN + ci);
        __half2 p01 = __floats2half2_rn(xv.x * sv.x, xv.y * sv.y);
        __half2 p23 = __floats2half2_rn(xv.z * sv.z, xv.w * sv.w);
        *(uint2*)(g_xh + e) = make_uint2(*(uint32_t*)&p01, *(uint32_t*)&p23);
    } else {
        int ci = blockIdx.x - XBLOCKS;
        int co = threadIdx.x;
        float s = 0.0f;
        #pragma unroll
        for (int tap = 0; tap < 9; ++tap) {
            size_t idx = (size_t)(tap * CIN + ci) * COUT + co;
            float w = kern[idx];
            g_wh[idx] = __float2half_rn(w);
            s = fmaf(w, w, s);
        }
        g_k2t[co * CIN + ci] = s;
    }
}

__global__ __launch_bounds__(256) void demod_kernel(const float* __restrict__ style) {
    int gw   = blockIdx.x * 8 + (threadIdx.x >> 5);
    int lane = threadIdx.x & 31;
    int b  = gw >> 8;
    int co = gw & 255;
    float acc = 0.0f;
    #pragma unroll
    for (int t = 0; t < 8; ++t) {
        int ci = t * 32 + lane;
        float s = style[b * CIN + ci];
        acc = fmaf(s * s, g_k2t[co * CIN + ci], acc);
    }
    #pragma unroll
    for (int o = 16; o > 0; o >>= 1)
        acc += __shfl_xor_sync(0xFFFFFFFF, acc, o);
    if (lane == 0) g_demod[b * COUT + co] = rsqrtf(acc + 1e-7f);
}

// ---------------- main mma.sync kernel: TMA-fed pipeline ----------------
// Tile/warp/fragment structure identical to the 456.8us kernel.
// Loads now issued by ONE thread via TMA; SAME-padding via TMA OOB zero-fill.
// A stage swizzle (TMA SW64) == old manual chunk^((row>>1)&3).  B stage =
// two 128B-wide halves (TMA SW128) == old chunk^(row&7) per half.
__global__ __launch_bounds__(256, 2) void conv_mma_kernel(
    const __grid_constant__ CUtensorMap tmA,
    const __grid_constant__ CUtensorMap tmB,
    float* __restrict__ out) {
    extern __shared__ char dsm[];
    const uint32_t base = (s2u(dsm) + 1023u) & ~1023u;
    const uint32_t stg0 = base + 1024u;
    const int tid  = threadIdx.x;
    const int wid  = tid >> 5;
    const int lane = tid & 31;
    const int wm = wid & 1;
    const int wn = wid >> 1;
    const int mt = blockIdx.y;       // 128 consecutive m = one image row
    const int n0 = blockIdx.x * 128;
    const int b  = mt >> 7;
    const int h  = mt & 127;
    const int m0 = mt * 128;

    if (tid == 0) {
        #pragma unroll
        for (int s = 0; s < STAGES; ++s) mbar_init(base + s * 8, 1);
        FENCE_ASYNC();
    }
    __syncthreads();

    // one-thread stage issue: A (4D, OOB-padded) + B (2 column halves)
    auto issue = [&](int kc) {
        const int slot = kc & (STAGES - 1);
        const uint32_t mb = base + slot * 8;
        const uint32_t sb = stg0 + (uint32_t)slot * STAGE_BYTES;
        const int tap = kc >> 3;
        const int ci0 = (kc & 7) << 5;
        const int dh  = tap / 3;
        const int dw  = tap - dh * 3;
        mbar_expect(mb, STAGE_BYTES);
        tma4(sb, &tmA, ci0, dw - 1, h + dh - 1, b, mb);
        tma2(sb + 8192u,  &tmB, n0,      kc * 32, mb);
        tma2(sb + 12288u, &tmB, n0 + 64, kc * 32, mb);
    };

    if (tid == 0) {
        issue(0); issue(1); issue(2);
    }

    // ldmatrix lane constants (identical to R16)
    const int lr = lane & 7;
    const int lg = lane >> 3;
    const int cg = lg >> 1;
    int rowA[4];
    #pragma unroll
    for (int mb = 0; mb < 4; ++mb)
        rowA[mb] = wm * 64 + mb * 16 + lr + (lg & 1) * 8;
    const int rkb = (lg & 1) * 8 + lr;

    float acc[4][4][4];
    #pragma unroll
    for (int mb = 0; mb < 4; ++mb)
        #pragma unroll
        for (int nb = 0; nb < 4; ++nb)
            #pragma unroll
            for (int q = 0; q < 4; ++q) acc[mb][nb][q] = 0.0f;

    #pragma unroll 4
    for (int kc = 0; kc < NKC; ++kc) {
        // top barrier: all warps finished reading stage (kc-1)&3 -> safe to
        // overwrite it with the TMA for stage kc+3 (same slot).
        __syncthreads();
        if (tid == 0 && kc + 3 < NKC) issue(kc + 3);
        mbar_wait(base + (kc & (STAGES - 1)) * 8, (kc >> 2) & 1);

        const uint32_t sb = stg0 + (uint32_t)(kc & (STAGES - 1)) * STAGE_BYTES;
        #pragma unroll
        for (int ks = 0; ks < 2; ++ks) {
            uint32_t a[4][4], bh[2][4];
            #pragma unroll
            for (int mb = 0; mb < 4; ++mb) {
                int ch = 2 * ks + cg;
                ldsm4(a[mb], sb + (uint32_t)(rowA[mb] * 64 +
                             ((ch ^ ((rowA[mb] >> 1) & 3)) * 16)));
            }
            #pragma unroll
            for (int h2 = 0; h2 < 2; ++h2) {
                int rk = ks * 16 + rkb;
                int ch = wn * 4 + h2 * 2 + cg;              // 0..15
                int half = ch >> 3;
                int c7   = ch & 7;
                ldsm4t(bh[h2], sb + 8192u + (uint32_t)(half * 4096 + rk * 128 +
                               ((c7 ^ (rk & 7)) * 16)));
            }
            #pragma unroll
            for (int mb = 0; mb < 4; ++mb)
                #pragma unroll
                for (int nb = 0; nb < 4; ++nb)
                    mma16816(acc[mb][nb], a[mb],
                             bh[nb >> 1][2 * (nb & 1)], bh[nb >> 1][2 * (nb & 1) + 1]);
        }
    }

    // ---- epilogue: demod + store (unchanged) ----
    const int mbase = m0 + wm * 64;
    const int nbase = n0 + wn * 32;
    const float* dmp = g_demod + b * COUT;
    float dm[4][2];
    #pragma unroll
    for (int nb = 0; nb < 4; ++nb) {
        int n = nbase + nb * 8 + (lane & 3) * 2;
        dm[nb][0] = __ldg(dmp + n);
        dm[nb][1] = __ldg(dmp + n + 1);
    }
    #pragma unroll
    for (int mb = 0; mb < 4; ++mb) {
        #pragma unroll
        for (int r2 = 0; r2 < 2; ++r2) {
            int m = mbase + mb * 16 + (lane >> 2) + r2 * 8;
            float* op = out + (size_t)m * COUT;
            #pragma unroll
            for (int nb = 0; nb < 4; ++nb) {
                int n = nbase + nb * 8 + (lane & 3) * 2;
                float2 v;
                v.x = acc[mb][nb][2 * r2]     * dm[nb][0];
                v.y = acc[mb][nb][2 * r2 + 1] * dm[nb][1];
                *(float2*)(op + n) = v;
            }
        }
    }
}

// ---------------- host launch ----------------
typedef CUresult (*EncFn)(CUtensorMap*, CUtensorMapDataType, cuuint32_t, void*,
                          const cuuint64_t*, const cuuint64_t*, const cuuint32_t*,
                          const cuuint32_t*, CUtensorMapInterleave, CUtensorMapSwizzle,
                          CUtensorMapL2promotion, CUtensorMapFloatOOBfill);

extern "C" void kernel_launch(void* const* d_in, const int* in_sizes, int n_in,
                              void* d_out, int out_size) {
    const float* x     = (const float*)d_in[0];   // (8,128,128,256)
    const float* style = (const float*)d_in[1];   // (8,256)
    const float* kern  = (const float*)d_in[2];   // (3,3,256,256)
    float* out = (float*)d_out;

    void* fp = nullptr;
    cudaDriverEntryPointQueryResult qr;
    cudaGetDriverEntryPoint("cuTensorMapEncodeTiled", &fp, cudaEnableDefault, &qr);
    EncFn enc = (EncFn)fp;

    void *p_xh, *p_wh;
    cudaGetSymbolAddress(&p_xh, g_xh);
    cudaGetSymbolAddress(&p_wh, g_wh);

    // A: 4D [CIN, W, H, B] fp16; box (32, 128, 1, 1); SW64 (rows = 64B)
    CUtensorMap tmA, tmB;
    {
        cuuint64_t dims[4]    = {256, 128, 128, 8};
        cuuint64_t strides[3] = {512, 65536, 8388608};     // bytes
        cuuint32_t box[4]     = {32, 128, 1, 1};
        cuuint32_t es[4]      = {1, 1, 1, 1};
        enc(&tmA, CU_TENSOR_MAP_DATA_TYPE_FLOAT16, 4, p_xh, dims, strides, box, es,
            CU_TENSOR_MAP_INTERLEAVE_NONE, CU_TENSOR_MAP_SWIZZLE_64B,
            CU_TENSOR_MAP_L2_PROMOTION_L2_128B, CU_TENSOR_MAP_FLOAT_OOB_FILL_NONE);
    }
    // B: 2D [COUT(n), KTOT(k)] fp16; box (64, 32); SW128 (rows = 128B)
    {
        cuuint64_t dims[2]    = {256, KTOT};
        cuuint64_t strides[1] = {512};                      // bytes
        cuuint32_t box[2]     = {64, 32};
        cuuint32_t es[2]      = {1, 1};
        enc(&tmB, CU_TENSOR_MAP_DATA_TYPE_FLOAT16, 2, p_wh, dims, strides, box, es,
            CU_TENSOR_MAP_INTERLEAVE_NONE, CU_TENSOR_MAP_SWIZZLE_128B,
            CU_TENSOR_MAP_L2_PROMOTION_L2_128B, CU_TENSOR_MAP_FLOAT_OOB_FILL_NONE);
    }

    pre_kernel<<<XBLOCKS + CIN, 256>>>(x, style, kern);
    demod_kernel<<<256, 256>>>(style);

    cudaFuncSetAttribute(conv_mma_kernel,
                         cudaFuncAttributeMaxDynamicSharedMemorySize, SMEM_REQ);
    dim3 grid(2, 1024);
    conv_mma_kernel<<<grid, 256, SMEM_REQ>>>(tmA, tmB, out);
}